// round 16
// baseline (speedup 1.0000x reference)
#include <cuda_runtime.h>

#define H 15
// Padded packed-weight layout (u64 {w,w} each), 16B-aligned pairs:
//  [0,30)    W1 k-major pairs: slot 2k+c = W1[c*H+k] * -log2e
//  [32,47)   b1 * -log2e
//  [48,288)  W2 transposed, 16/row: slot 48+16k+j = W2[j*H+k]  (j<15, pad 0)
//  [288,303) b2 * -log2e
//  [304,544) W3 transposed, 16/row: slot 304+16k+j = W3[j*H+k]
//  [544,559) b3 * -log2e
//  [560,576) W4[j] (pad 0)
//  [576]     b4 * -log2e
#define NSLOT 580

typedef unsigned long long u64;

__device__ u64 g_packed[NSLOT];
__constant__ u64 cw2n[NSLOT];

// ---- packed f32x2 helpers (sm_100+ PTX) ----
__device__ __forceinline__ u64 pk(float a, float b) {
    u64 r; asm("mov.b64 %0,{%1,%2};" : "=l"(r) : "f"(a), "f"(b)); return r;
}
__device__ __forceinline__ void upk(u64 v, float& a, float& b) {
    asm("mov.b64 {%0,%1},%2;" : "=f"(a), "=f"(b) : "l"(v));
}
__device__ __forceinline__ u64 fma2(u64 a, u64 b, u64 c) {
    u64 r; asm("fma.rn.f32x2 %0,%1,%2,%3;" : "=l"(r) : "l"(a), "l"(b), "l"(c)); return r;
}
__device__ __forceinline__ u64 mul2(u64 a, u64 b) {
    u64 r; asm("mul.rn.f32x2 %0,%1,%2;" : "=l"(r) : "l"(a), "l"(b)); return r;
}

// One LDC.128 -> two independent u64 ("l" class, f32x2-compatible).
__device__ __forceinline__ void ldc2(u64 cb, int slot, u64& w0, u64& w1) {
    asm("ld.const.v2.u64 {%0,%1},[%2];"
        : "=l"(w0), "=l"(w1) : "l"(cb + (u64)(slot) * 8ull));
}

// t = -log2e * a arrives directly from the pre-scaled GEMV.
// g = t * rcp(1 + ex2(t)) = -log2e * SiLU(a); compensation folds into the
// next (linear) layer, whose weights therefore stay unscaled.
__device__ __forceinline__ u64 act2(u64 t) {
    float t0, t1; upk(t, t0, t1);
    float e0, e1;
    asm("ex2.approx.f32 %0,%1;" : "=f"(e0) : "f"(t0));
    asm("ex2.approx.f32 %0,%1;" : "=f"(e1) : "f"(t1));
    float d0 = e0 + 1.0f, d1 = e1 + 1.0f;
    float r0, r1;
    asm("rcp.approx.f32 %0,%1;" : "=f"(r0) : "f"(d0));
    asm("rcp.approx.f32 %0,%1;" : "=f"(r1) : "f"(d1));
    return mul2(t, pk(r0, r1));
}

// final sigmoid: sigma(a) = rcp(1 + ex2(t)), t = -log2e * a
__device__ __forceinline__ void sig2s(u64 t, float& r0, float& r1) {
    float t0, t1; upk(t, t0, t1);
    float e0, e1;
    asm("ex2.approx.f32 %0,%1;" : "=f"(e0) : "f"(t0));
    asm("ex2.approx.f32 %0,%1;" : "=f"(e1) : "f"(t1));
    float d0 = e0 + 1.0f, d1 = e1 + 1.0f;
    asm("rcp.approx.f32 %0,%1;" : "=f"(r0) : "f"(d0));
    asm("rcp.approx.f32 %0,%1;" : "=f"(r1) : "f"(d1));
}

#define NLOG2E (-1.4426950408889634f)

__global__ void prep_kernel(const float* __restrict__ W1, const float* __restrict__ b1,
                            const float* __restrict__ W2, const float* __restrict__ b2,
                            const float* __restrict__ W3, const float* __restrict__ b3,
                            const float* __restrict__ W4, const float* __restrict__ b4) {
    int i = threadIdx.x;
    if (i >= NSLOT) return;
    float v = 0.0f;   // pads stay zero
    if      (i < 30)              { int k = i >> 1, c = i & 1; v = W1[c * H + k] * NLOG2E; }
    else if (i >= 32  && i < 47)  { v = b1[i - 32] * NLOG2E; }
    else if (i >= 48  && i < 288) { int l = i - 48,  k = l >> 4, j = l & 15; if (j < H) v = W2[j * H + k]; }
    else if (i >= 288 && i < 303) { v = b2[i - 288] * NLOG2E; }
    else if (i >= 304 && i < 544) { int l = i - 304, k = l >> 4, j = l & 15; if (j < H) v = W3[j * H + k]; }
    else if (i >= 544 && i < 559) { v = b3[i - 544] * NLOG2E; }
    else if (i >= 560 && i < 575) { v = W4[i - 560]; }
    else if (i == 576)            { v = b4[0] * NLOG2E; }
    u64 p; asm("mov.b64 %0,{%1,%1};" : "=l"(p) : "f"(v));
    g_packed[i] = p;
}

// 2 rows per thread, packed f32x2 math, paired weights via LDC.128
// (inline-asm ld.const.v2.u64 keeps both halves in "l" class for fma2).
__global__ __launch_bounds__(128) void mlp2_kernel(const float4* __restrict__ x,
                                                   float2* __restrict__ out,
                                                   int npair) {
    // const-space base address for vector weight loads
    u64 cb;
    {
        u64 g = (u64)cw2n;   // generic address of __constant__ array
        asm("cvta.to.const.u64 %0,%1;" : "=l"(cb) : "l"(g));
    }

    int i = blockIdx.x * blockDim.x + threadIdx.x;
    if (i >= npair) return;

    float4 xv = x[i];                  // {x0,y0,x1,y1} = rows 2i, 2i+1
    u64 xx = pk(xv.x, xv.z);
    u64 yy = pk(xv.y, xv.w);

    u64 h1[H], h2[H];

    // Layer 1: Linear(2,H)*-log2e -> act  (one LDC.128 per k)
#pragma unroll
    for (int k = 0; k < H; k++) {
        u64 w0, w1; ldc2(cb, 2 * k, w0, w1);
        u64 t = fma2(xx, w0, fma2(yy, w1, cw2n[32 + k]));
        h1[k] = act2(t);
    }

    // Layer 2: Linear(H,H) -> act  (7x LDC.128 + 1 LDC.64 per k)
#pragma unroll
    for (int k = 0; k < H; k++) {
        u64 t = cw2n[288 + k];
#pragma unroll
        for (int jj = 0; jj < 7; jj++) {
            u64 w0, w1; ldc2(cb, 48 + 16 * k + 2 * jj, w0, w1);
            t = fma2(h1[2 * jj], w0, t);
            t = fma2(h1[2 * jj + 1], w1, t);
        }
        t = fma2(h1[14], cw2n[48 + 16 * k + 14], t);
        h2[k] = act2(t);
    }

    // Layer 3 (reuse h1)
#pragma unroll
    for (int k = 0; k < H; k++) {
        u64 t = cw2n[544 + k];
#pragma unroll
        for (int jj = 0; jj < 7; jj++) {
            u64 w0, w1; ldc2(cb, 304 + 16 * k + 2 * jj, w0, w1);
            t = fma2(h2[2 * jj], w0, t);
            t = fma2(h2[2 * jj + 1], w1, t);
        }
        t = fma2(h2[14], cw2n[304 + 16 * k + 14], t);
        h1[k] = act2(t);
    }

    // Layer 4 + sigmoid
    u64 t = cw2n[576];
#pragma unroll
    for (int jj = 0; jj < 7; jj++) {
        u64 w0, w1; ldc2(cb, 560 + 2 * jj, w0, w1);
        t = fma2(h1[2 * jj], w0, t);
        t = fma2(h1[2 * jj + 1], w1, t);
    }
    t = fma2(h1[14], cw2n[560 + 14], t);

    float s0, s1;
    sig2s(t, s0, s1);
    out[i] = make_float2(s0, s1);
}

extern "C" void kernel_launch(void* const* d_in, const int* in_sizes, int n_in,
                              void* d_out, int out_size) {
    // Inputs: x, W1, b1, W2, b2, W3, b3, W4, b4
    const float* x = (const float*)d_in[0];

    prep_kernel<<<1, 608>>>((const float*)d_in[1], (const float*)d_in[2],
                            (const float*)d_in[3], (const float*)d_in[4],
                            (const float*)d_in[5], (const float*)d_in[6],
                            (const float*)d_in[7], (const float*)d_in[8]);

    void* src = nullptr;
    cudaGetSymbolAddress(&src, g_packed);  // host-side query, capture-safe
    cudaMemcpyToSymbolAsync(cw2n, src, NSLOT * sizeof(u64), 0,
                            cudaMemcpyDeviceToDevice, 0);

    int n = in_sizes[0] / 2;   // rows
    int npair = n / 2;         // 2 rows per thread
    int threads = 128;
    int blocks = (npair + threads - 1) / threads;
    mlp2_kernel<<<blocks, threads>>>((const float4*)x, (float2*)d_out, npair);
}